// round 16
// baseline (speedup 1.0000x reference)
#include <cuda_runtime.h>
#include <cuda_fp16.h>
#include <math.h>
#include <stdint.h>

// Problem constants
#define N_TOT 200000
#define D_DIM 128
#define T_DIM 8
#define P_DIM 2000
#define NP_DIM 9
#define H_DIM 2048
#define PT (P_DIM * T_DIM)
#define TD (T_DIM * D_DIM)          // 1024
#define SLOTS 64
#define NBINS 16

// ---------------- scratch ----------------------------------------------------
__device__ int    g_cnt[PT];
__device__ int    g_idx[PT * SLOTS];
__device__ float  g_task_bin[NBINS][TD];
__device__ float  g_tcnt_bin[NBINS][T_DIM];
__device__ int    g_first[P_DIM];
__device__ __half g_fph[P_DIM * TD];
__device__ __half g_W1h[TD * H_DIM];
__device__ __half g_W2h[H_DIM * H_DIM];
__device__ __half g_h1h[P_DIM * H_DIM];
__device__ __half g_h2h[P_DIM * H_DIM];

// ---------------- helpers ------------------------------------------------------
__device__ __forceinline__ uint2 hpack4(float4 m) {
    __half2 a = __floats2half2_rn(m.x, m.y);
    __half2 b = __floats2half2_rn(m.z, m.w);
    uint2 o;
    o.x = *reinterpret_cast<uint32_t*>(&a);
    o.y = *reinterpret_cast<uint32_t*>(&b);
    return o;
}

// ---------------- K0: init ------------------------------------------------------
__global__ void k_init() {
    int i = blockIdx.x * blockDim.x + threadIdx.x;
    int stride = gridDim.x * blockDim.x;
    for (int j = i; j < PT; j += stride) g_cnt[j] = 0;
    for (int j = i; j < NBINS * TD; j += stride) ((float*)g_task_bin)[j] = 0.0f;
    for (int j = i; j < NBINS * T_DIM; j += stride) ((float*)g_tcnt_bin)[j] = 0.0f;
    for (int j = i; j < P_DIM; j += stride) g_first[j] = N_TOT;
}

// ---------------- K1: placement --------------------------------------------------
__global__ void k_place(const int* __restrict__ tasks,
                        const int* __restrict__ tasks_mask,
                        const int* __restrict__ patient_ids,
                        const int* __restrict__ phenos_mask) {
    int i = blockIdx.x * blockDim.x + threadIdx.x;
    if (i >= N_TOT) return;
    if (tasks_mask[i] != 1 || phenos_mask[i] != 1) return;
    int t = tasks[i];
    int p = patient_ids[i];
    int seg = p * T_DIM + t;
    int pos = atomicAdd(&g_cnt[seg], 1);
    if (pos < SLOTS) g_idx[seg * SLOTS + pos] = i;
    atomicMin(&g_first[p], i);
}

// ---------------- K2: segment reduce (one warp per segment) ----------------------
__global__ __launch_bounds__(256) void k_segreduce(const float* __restrict__ motion_z) {
    int seg = (blockIdx.x * blockDim.x + threadIdx.x) >> 5;
    int lane = threadIdx.x & 31;
    if (seg >= PT) return;
    int t = seg & (T_DIM - 1);
    int n = g_cnt[seg];
    if (n <= 0) return;
    int nn = n < SLOTS ? n : SLOTS;
    int bin = blockIdx.x & (NBINS - 1);

    int idx0 = g_idx[seg * SLOTS + lane];
    int idx1 = g_idx[seg * SLOTS + 32 + lane];

    float4 acc = make_float4(0.f, 0.f, 0.f, 0.f);
    int r = 0;
    for (; r + 2 <= nn; r += 2) {
        int iA = (r < 32) ? __shfl_sync(0xFFFFFFFF, idx0, r)
                          : __shfl_sync(0xFFFFFFFF, idx1, r - 32);
        int rb = r + 1;
        int iB = (rb < 32) ? __shfl_sync(0xFFFFFFFF, idx0, rb)
                           : __shfl_sync(0xFFFFFFFF, idx1, rb - 32);
        float4 vA = reinterpret_cast<const float4*>(motion_z + (size_t)iA * D_DIM)[lane];
        float4 vB = reinterpret_cast<const float4*>(motion_z + (size_t)iB * D_DIM)[lane];
        acc.x += vA.x + vB.x;
        acc.y += vA.y + vB.y;
        acc.z += vA.z + vB.z;
        acc.w += vA.w + vB.w;
    }
    if (r < nn) {
        int iA = (r < 32) ? __shfl_sync(0xFFFFFFFF, idx0, r)
                          : __shfl_sync(0xFFFFFFFF, idx1, r - 32);
        float4 vA = reinterpret_cast<const float4*>(motion_z + (size_t)iA * D_DIM)[lane];
        acc.x += vA.x; acc.y += vA.y; acc.z += vA.z; acc.w += vA.w;
    }

    float* ts = g_task_bin[bin] + t * D_DIM + lane * 4;
    atomicAdd(ts + 0, acc.x);
    atomicAdd(ts + 1, acc.y);
    atomicAdd(ts + 2, acc.z);
    atomicAdd(ts + 3, acc.w);
    if (lane == 0) atomicAdd(&g_tcnt_bin[bin][t], (float)n);

    float inv = 1.0f / (float)n;
    float4 m = make_float4(acc.x * inv, acc.y * inv, acc.z * inv, acc.w * inv);
    *reinterpret_cast<uint2*>(g_fph + (size_t)seg * D_DIM + lane * 4) = hpack4(m);
}

// ---------------- K3: fallback for empty cells ------------------------------------
__global__ __launch_bounds__(256) void k_fallback() {
    int seg = (blockIdx.x * blockDim.x + threadIdx.x) >> 5;
    int lane = threadIdx.x & 31;
    if (seg >= PT) return;
    if (g_cnt[seg] > 0) return;
    int t = seg & (T_DIM - 1);

    float tc = 0.0f;
#pragma unroll
    for (int b = 0; b < NBINS; b++) tc += g_tcnt_bin[b][t];
    tc = fmaxf(tc, 1.0f);

    float4 s = make_float4(0.f, 0.f, 0.f, 0.f);
#pragma unroll
    for (int b = 0; b < NBINS; b++) {
        const float4 v = *reinterpret_cast<const float4*>(
            g_task_bin[b] + t * D_DIM + lane * 4);
        s.x += v.x; s.y += v.y; s.z += v.z; s.w += v.w;
    }
    float inv = 1.0f / tc;
    float4 m = make_float4(s.x * inv, s.y * inv, s.z * inv, s.w * inv);
    *reinterpret_cast<uint2*>(g_fph + (size_t)seg * D_DIM + lane * 4) = hpack4(m);
}

// ---------------- K4: uni_phenos gather -------------------------------------------
__global__ void k_uni_phenos(const float* __restrict__ phenos, float* __restrict__ out_uni) {
    int idx = blockIdx.x * blockDim.x + threadIdx.x;
    if (idx >= P_DIM * NP_DIM) return;
    int p = idx / NP_DIM;
    int j = idx - p * NP_DIM;
    int f = g_first[p];
    if (f > N_TOT - 1) f = N_TOT - 1;
    out_uni[idx] = phenos[(size_t)f * NP_DIM + j];
}

// ---------------- K5: merged fp32 -> fp16 conversion ------------------------------
__global__ void k_cvt2(const float* __restrict__ s1, __half* __restrict__ d1, int n1_4,
                       const float* __restrict__ s2, __half* __restrict__ d2, int n2_4) {
    int i = blockIdx.x * blockDim.x + threadIdx.x;
    if (i < n1_4) {
        float4 v = reinterpret_cast<const float4*>(s1)[i];
        *reinterpret_cast<uint2*>(d1 + (size_t)i * 4) = hpack4(v);
    } else {
        int j = i - n1_4;
        if (j < n2_4) {
            float4 v = reinterpret_cast<const float4*>(s2)[j];
            *reinterpret_cast<uint2*>(d2 + (size_t)j * 4) = hpack4(v);
        }
    }
}

// =================================================================================
// fp16 mma.sync GEMM, block tile 128x128, BK=64, 2-stage cp.async, fp16 output.
// 256 threads (8 warps as 2x4), warp tile 64x32, __launch_bounds__(256,2):
// 2 CTAs/SM hide stage-boundary bubbles; 256-block grid fills all 148 SMs.
// =================================================================================
#define A_STRIDE 72                                   // 64 data + 8 pad
#define B_STRIDE 136                                  // 128 data + 8 pad
#define SM_A 0
#define SM_B (128 * A_STRIDE)                         // 9216
#define STAGE_ELTS (SM_B + 64 * B_STRIDE)             // 17920 elts
#define STAGE_BYTES (STAGE_ELTS * 2)                  // 35840
#define SMEM_BYTES (2 * STAGE_BYTES)                  // 71680 bytes (2 CTAs = 143KB/SM)

__device__ __forceinline__ void cp16(uint32_t dst, const void* src, bool pred) {
    int sz = pred ? 16 : 0;
    asm volatile("cp.async.cg.shared.global [%0], [%1], 16, %2;\n"
                 :: "r"(dst), "l"(src), "r"(sz));
}
__device__ __forceinline__ void cp_commit() {
    asm volatile("cp.async.commit_group;\n");
}
template <int NG>
__device__ __forceinline__ void cp_wait() {
    asm volatile("cp.async.wait_group %0;\n" :: "n"(NG));
}
__device__ __forceinline__ void ldsm_x4(uint32_t* r, uint32_t addr) {
    asm volatile("ldmatrix.sync.aligned.m8n8.x4.shared.b16 {%0,%1,%2,%3}, [%4];"
                 : "=r"(r[0]), "=r"(r[1]), "=r"(r[2]), "=r"(r[3]) : "r"(addr));
}
__device__ __forceinline__ void ldsm_x4_t(uint32_t* r, uint32_t addr) {
    asm volatile("ldmatrix.sync.aligned.m8n8.x4.trans.shared.b16 {%0,%1,%2,%3}, [%4];"
                 : "=r"(r[0]), "=r"(r[1]), "=r"(r[2]), "=r"(r[3]) : "r"(addr));
}
__device__ __forceinline__ void mma_f16(float* d, const uint32_t* a, uint32_t b0, uint32_t b1) {
    asm volatile("mma.sync.aligned.m16n8k16.row.col.f32.f16.f16.f32 "
                 "{%0,%1,%2,%3},{%4,%5,%6,%7},{%8,%9},{%0,%1,%2,%3};"
                 : "+f"(d[0]), "+f"(d[1]), "+f"(d[2]), "+f"(d[3])
                 : "r"(a[0]), "r"(a[1]), "r"(a[2]), "r"(a[3]), "r"(b0), "r"(b1));
}

// stage loader (BK=64, 256 threads): A 1024 chunks -> 4/thread, B 1024 chunks -> 4/thread
__device__ __forceinline__ void load_stage(
    uint32_t stage, const __half* A, const __half* B,
    int M, int N, int K, int blockM, int blockN, int k0, int tid) {
    // A: 128 rows x 8 chunks(16B) = 1024
#pragma unroll
    for (int i = 0; i < 4; i++) {
        int c = tid + i * 256;
        int arow = c >> 3;
        int achk = (c & 7) << 3;
        int grow = blockM + arow;
        bool ap = grow < M;
        size_t goff = (size_t)grow * K + k0 + achk;
        uint32_t soff = stage + (uint32_t)((arow * A_STRIDE + achk) * 2);
        cp16(soff + SM_A * 2, A + goff, ap);
    }
    // B: 64 rows x 16 chunks(16B) = 1024
#pragma unroll
    for (int i = 0; i < 4; i++) {
        int idx = tid + i * 256;
        int brow = idx >> 4;
        int bchk = (idx & 15) << 3;
        size_t gb = (size_t)(k0 + brow) * N + blockN + bchk;
        uint32_t sb = stage + (uint32_t)((brow * B_STRIDE + bchk) * 2);
        cp16(sb + SM_B * 2, B + gb, true);
    }
}

__global__ __launch_bounds__(256, 2) void k_mma_gemm(
    int M, int N, int K,
    const __half* __restrict__ A, const __half* __restrict__ B,
    const float* __restrict__ bias,
    __half* __restrict__ Ch) {
    extern __shared__ char sm_raw[];
    const uint32_t smbase = (uint32_t)__cvta_generic_to_shared(sm_raw);

    const int tid = threadIdx.x;
    const int lane = tid & 31;
    const int wid = tid >> 5;
    const int warpM = wid >> 2;     // 0..1
    const int warpN = wid & 3;      // 0..3
    const int blockM = blockIdx.y * 128;
    const int blockN = blockIdx.x * 128;

    float acc[4][4][4];
#pragma unroll
    for (int i = 0; i < 4; i++)
#pragma unroll
        for (int j = 0; j < 4; j++)
#pragma unroll
            for (int c = 0; c < 4; c++) acc[i][j][c] = 0.0f;

    const int lq = lane >> 4;
    const int lr = lane & 15;
    const int nStages = K >> 6;

    load_stage(smbase, A, B, M, N, K, blockM, blockN, 0, tid);
    cp_commit();

    for (int t = 0; t < nStages; t++) {
        if (t + 1 < nStages) {
            load_stage(smbase + (uint32_t)(((t + 1) & 1) * STAGE_BYTES),
                       A, B, M, N, K, blockM, blockN, (t + 1) << 6, tid);
            cp_commit();
            cp_wait<1>();
        } else {
            cp_wait<0>();
        }
        __syncthreads();

        const uint32_t stage = smbase + (uint32_t)((t & 1) * STAGE_BYTES);
#pragma unroll
        for (int kk = 0; kk < 64; kk += 16) {
            uint32_t a_r[4][4], b_r[2][4];
#pragma unroll
            for (int im = 0; im < 4; im++) {
                int row = warpM * 64 + im * 16 + lr;
                int col = kk + 8 * lq;
                uint32_t addr = stage + (uint32_t)((row * A_STRIDE + col) * 2);
                ldsm_x4(a_r[im], addr + SM_A * 2);
            }
#pragma unroll
            for (int ip = 0; ip < 2; ip++) {
                int row = kk + lr;
                int col = warpN * 32 + ip * 16 + 8 * lq;
                uint32_t addr = stage + (uint32_t)((row * B_STRIDE + col) * 2);
                ldsm_x4_t(b_r[ip], addr + SM_B * 2);
            }
#pragma unroll
            for (int im = 0; im < 4; im++) {
#pragma unroll
                for (int in = 0; in < 4; in++) {
                    int ip = in >> 1, h = (in & 1) << 1;
                    mma_f16(acc[im][in], a_r[im], b_r[ip][h], b_r[ip][h + 1]);
                }
            }
        }
        __syncthreads();
    }

    // epilogue: bias + relu -> fp16
    const int g = lane >> 2, tg = lane & 3;
#pragma unroll
    for (int im = 0; im < 4; im++) {
#pragma unroll
        for (int in = 0; in < 4; in++) {
            int col = blockN + warpN * 32 + in * 8 + tg * 2;
            float b0 = bias[col], b1 = bias[col + 1];
            int row0 = blockM + warpM * 64 + im * 16 + g;
            float v0 = fmaxf(acc[im][in][0] + b0, 0.f);
            float v1 = fmaxf(acc[im][in][1] + b1, 0.f);
            float v2 = fmaxf(acc[im][in][2] + b0, 0.f);
            float v3 = fmaxf(acc[im][in][3] + b1, 0.f);
            if (row0 < M) {
                __half2 hh = __floats2half2_rn(v0, v1);
                *reinterpret_cast<__half2*>(Ch + (size_t)row0 * N + col) = hh;
            }
            if (row0 + 8 < M) {
                __half2 hh = __floats2half2_rn(v2, v3);
                *reinterpret_cast<__half2*>(Ch + (size_t)(row0 + 8) * N + col) = hh;
            }
        }
    }
}

// ---------------- K6: head (fp16 h2) ----------------------------------------------
__global__ __launch_bounds__(256) void k_head(
    const __half* __restrict__ h, const float* __restrict__ W3,
    const float* __restrict__ b3,
    float* __restrict__ out_sig, float* __restrict__ out_latent) {
    int p = blockIdx.x;
    int tid = threadIdx.x;
    int lane = tid & 31;
    int wid = tid >> 5;

    float acc[NP_DIM];
#pragma unroll
    for (int j = 0; j < NP_DIM; j++) acc[j] = 0.0f;

    const __half* hrow = h + (size_t)p * H_DIM;
    for (int k = tid; k < H_DIM; k += 256) {
        float hv = __half2float(hrow[k]);
        const float* w = W3 + (size_t)k * NP_DIM;
#pragma unroll
        for (int j = 0; j < NP_DIM; j++) acc[j] = fmaf(hv, w[j], acc[j]);
    }
#pragma unroll
    for (int j = 0; j < NP_DIM; j++) {
#pragma unroll
        for (int s = 16; s > 0; s >>= 1)
            acc[j] += __shfl_down_sync(0xFFFFFFFF, acc[j], s);
    }
    __shared__ float smem[8][NP_DIM];
    if (lane == 0) {
#pragma unroll
        for (int j = 0; j < NP_DIM; j++) smem[wid][j] = acc[j];
    }
    __syncthreads();
    if (tid < NP_DIM) {
        float s = 0.0f;
#pragma unroll
        for (int w = 0; w < 8; w++) s += smem[w][tid];
        float latent = s + b3[tid];
        out_latent[p * NP_DIM + tid] = latent;
        out_sig[p * NP_DIM + tid] = 1.0f / (1.0f + expf(-latent));
    }
}

// ---------------- launch ----------------------------------------------------
extern "C" void kernel_launch(void* const* d_in, const int* in_sizes, int n_in,
                              void* d_out, int out_size) {
    const float* motion_z    = (const float*)d_in[0];
    const int*   tasks       = (const int*)d_in[1];
    const int*   tasks_mask  = (const int*)d_in[2];
    const int*   patient_ids = (const int*)d_in[3];
    const float* phenos      = (const float*)d_in[4];
    const int*   phenos_mask = (const int*)d_in[5];
    const float* W1          = (const float*)d_in[6];
    const float* b1          = (const float*)d_in[7];
    const float* W2          = (const float*)d_in[8];
    const float* b2          = (const float*)d_in[9];
    const float* W3          = (const float*)d_in[10];
    const float* b3          = (const float*)d_in[11];

    float* out_sig    = (float*)d_out;
    float* out_uni    = out_sig + P_DIM * NP_DIM;
    float* out_latent = out_uni + P_DIM * NP_DIM;

    __half *fph, *w1h, *w2h, *h1h, *h2h;
    cudaGetSymbolAddress((void**)&fph, g_fph);
    cudaGetSymbolAddress((void**)&w1h, g_W1h);
    cudaGetSymbolAddress((void**)&w2h, g_W2h);
    cudaGetSymbolAddress((void**)&h1h, g_h1h);
    cudaGetSymbolAddress((void**)&h2h, g_h2h);

    cudaFuncSetAttribute(k_mma_gemm, cudaFuncAttributeMaxDynamicSharedMemorySize, SMEM_BYTES);

    const int n1_4 = TD * H_DIM / 4;
    const int n2_4 = H_DIM * H_DIM / 4;
    k_cvt2<<<(n1_4 + n2_4 + 255) / 256, 256>>>(W1, w1h, n1_4, W2, w2h, n2_4);   // 1
    k_init<<<64, 256>>>();                                                      // 2
    k_place<<<(N_TOT + 255) / 256, 256>>>(tasks, tasks_mask, patient_ids,
                                          phenos_mask);                         // 3
    k_segreduce<<<PT / 8, 256>>>(motion_z);                                     // 4
    k_fallback<<<PT / 8, 256>>>();                                              // 5

    // GEMM1: [2000,1024] @ [1024,2048] -> h1 (relu, fp16 out)                  // 6
    {
        dim3 grid(H_DIM / 128, (P_DIM + 127) / 128);   // 16 x 16 = 256 blocks
        k_mma_gemm<<<grid, 256, SMEM_BYTES>>>(P_DIM, H_DIM, TD, fph, w1h, b1, h1h);
    }
    // GEMM2: [2000,2048] @ [2048,2048] -> h2 (relu, fp16 out)                  // 7
    {
        dim3 grid(H_DIM / 128, (P_DIM + 127) / 128);
        k_mma_gemm<<<grid, 256, SMEM_BYTES>>>(P_DIM, H_DIM, H_DIM, h1h, w2h, b2, h2h);
    }
    k_uni_phenos<<<(P_DIM * NP_DIM + 255) / 256, 256>>>(phenos, out_uni);       // 8
    k_head<<<P_DIM, 256>>>(h2h, W3, b3, out_sig, out_latent);                   // 9
}

// round 17
// speedup vs baseline: 1.0250x; 1.0250x over previous
#include <cuda_runtime.h>
#include <cuda_fp16.h>
#include <math.h>
#include <stdint.h>

// Problem constants
#define N_TOT 200000
#define D_DIM 128
#define T_DIM 8
#define P_DIM 2000
#define NP_DIM 9
#define H_DIM 2048
#define PT (P_DIM * T_DIM)
#define TD (T_DIM * D_DIM)          // 1024
#define SLOTS 64
#define NBINS 16

#define N1_4 (TD * H_DIM / 4)       // 524288  W1 float4 count
#define N2_4 (H_DIM * H_DIM / 4)    // 1048576 W2 float4 count
#define CVT_BLOCKS ((N1_4 + N2_4) / 256)   // 6144
#define COMBO_GRID 8192             // 2048 seg slots (2000 used) + 6144 cvt slots

// ---------------- scratch ----------------------------------------------------
__device__ int    g_cnt[PT];
__device__ int    g_idx[PT * SLOTS];
__device__ float  g_task_bin[NBINS][TD];
__device__ float  g_tcnt_bin[NBINS][T_DIM];
__device__ int    g_first[P_DIM];
__device__ __half g_fph[P_DIM * TD];
__device__ __half g_W1h[TD * H_DIM];
__device__ __half g_W2h[H_DIM * H_DIM];
__device__ __half g_h1h[P_DIM * H_DIM];
__device__ __half g_h2h[P_DIM * H_DIM];

// ---------------- helpers ------------------------------------------------------
__device__ __forceinline__ uint2 hpack4(float4 m) {
    __half2 a = __floats2half2_rn(m.x, m.y);
    __half2 b = __floats2half2_rn(m.z, m.w);
    uint2 o;
    o.x = *reinterpret_cast<uint32_t*>(&a);
    o.y = *reinterpret_cast<uint32_t*>(&b);
    return o;
}

// ---------------- K0: init ------------------------------------------------------
__global__ void k_init() {
    int i = blockIdx.x * blockDim.x + threadIdx.x;
    int stride = gridDim.x * blockDim.x;
    for (int j = i; j < PT; j += stride) g_cnt[j] = 0;
    for (int j = i; j < NBINS * TD; j += stride) ((float*)g_task_bin)[j] = 0.0f;
    for (int j = i; j < NBINS * T_DIM; j += stride) ((float*)g_tcnt_bin)[j] = 0.0f;
    for (int j = i; j < P_DIM; j += stride) g_first[j] = N_TOT;
}

// ---------------- K1: placement --------------------------------------------------
__global__ void k_place(const int* __restrict__ tasks,
                        const int* __restrict__ tasks_mask,
                        const int* __restrict__ patient_ids,
                        const int* __restrict__ phenos_mask) {
    int i = blockIdx.x * blockDim.x + threadIdx.x;
    if (i >= N_TOT) return;
    if (tasks_mask[i] != 1 || phenos_mask[i] != 1) return;
    int t = tasks[i];
    int p = patient_ids[i];
    int seg = p * T_DIM + t;
    int pos = atomicAdd(&g_cnt[seg], 1);
    if (pos < SLOTS) g_idx[seg * SLOTS + pos] = i;
    atomicMin(&g_first[p], i);
}

// ---------------- K2: combined segreduce + weight convert -------------------------
// Block-striped: bid % 4 == 0 -> segment-reduce work; else -> fp32->fp16 convert.
// Interleaving lets the bandwidth-bound convert stream fill the latency stalls of
// the gather-bound segreduce on the same SMs.
__global__ __launch_bounds__(256) void k_combo(
    const float* __restrict__ motion_z,
    const float* __restrict__ W1, __half* __restrict__ w1h,
    const float* __restrict__ W2, __half* __restrict__ w2h) {
    int bid = blockIdx.x;
    if ((bid & 3) == 0) {
        // ---- segreduce path: seg-block id 0..2047 (2000 used) ----
        int sb = bid >> 2;
        int seg = sb * 8 + (threadIdx.x >> 5);
        int lane = threadIdx.x & 31;
        if (seg >= PT) return;
        int t = seg & (T_DIM - 1);
        int n = g_cnt[seg];
        if (n <= 0) return;
        int nn = n < SLOTS ? n : SLOTS;
        int bin = sb & (NBINS - 1);

        int idx0 = g_idx[seg * SLOTS + lane];
        int idx1 = g_idx[seg * SLOTS + 32 + lane];

        float4 acc = make_float4(0.f, 0.f, 0.f, 0.f);
        int r = 0;
        for (; r + 2 <= nn; r += 2) {
            int iA = (r < 32) ? __shfl_sync(0xFFFFFFFF, idx0, r)
                              : __shfl_sync(0xFFFFFFFF, idx1, r - 32);
            int rb = r + 1;
            int iB = (rb < 32) ? __shfl_sync(0xFFFFFFFF, idx0, rb)
                               : __shfl_sync(0xFFFFFFFF, idx1, rb - 32);
            float4 vA = reinterpret_cast<const float4*>(motion_z + (size_t)iA * D_DIM)[lane];
            float4 vB = reinterpret_cast<const float4*>(motion_z + (size_t)iB * D_DIM)[lane];
            acc.x += vA.x + vB.x;
            acc.y += vA.y + vB.y;
            acc.z += vA.z + vB.z;
            acc.w += vA.w + vB.w;
        }
        if (r < nn) {
            int iA = (r < 32) ? __shfl_sync(0xFFFFFFFF, idx0, r)
                              : __shfl_sync(0xFFFFFFFF, idx1, r - 32);
            float4 vA = reinterpret_cast<const float4*>(motion_z + (size_t)iA * D_DIM)[lane];
            acc.x += vA.x; acc.y += vA.y; acc.z += vA.z; acc.w += vA.w;
        }

        float* ts = g_task_bin[bin] + t * D_DIM + lane * 4;
        atomicAdd(ts + 0, acc.x);
        atomicAdd(ts + 1, acc.y);
        atomicAdd(ts + 2, acc.z);
        atomicAdd(ts + 3, acc.w);
        if (lane == 0) atomicAdd(&g_tcnt_bin[bin][t], (float)n);

        float inv = 1.0f / (float)n;
        float4 m = make_float4(acc.x * inv, acc.y * inv, acc.z * inv, acc.w * inv);
        *reinterpret_cast<uint2*>(g_fph + (size_t)seg * D_DIM + lane * 4) = hpack4(m);
    } else {
        // ---- convert path: cvt-block id 0..6143 ----
        int cb = bid - ((bid + 3) >> 2);
        int i = cb * 256 + threadIdx.x;
        if (i < N1_4) {
            float4 v = reinterpret_cast<const float4*>(W1)[i];
            *reinterpret_cast<uint2*>(w1h + (size_t)i * 4) = hpack4(v);
        } else {
            int j = i - N1_4;
            if (j < N2_4) {
                float4 v = reinterpret_cast<const float4*>(W2)[j];
                *reinterpret_cast<uint2*>(w2h + (size_t)j * 4) = hpack4(v);
            }
        }
    }
}

// ---------------- K3: fallback for empty cells ------------------------------------
__global__ __launch_bounds__(256) void k_fallback() {
    int seg = (blockIdx.x * blockDim.x + threadIdx.x) >> 5;
    int lane = threadIdx.x & 31;
    if (seg >= PT) return;
    if (g_cnt[seg] > 0) return;
    int t = seg & (T_DIM - 1);

    float tc = 0.0f;
#pragma unroll
    for (int b = 0; b < NBINS; b++) tc += g_tcnt_bin[b][t];
    tc = fmaxf(tc, 1.0f);

    float4 s = make_float4(0.f, 0.f, 0.f, 0.f);
#pragma unroll
    for (int b = 0; b < NBINS; b++) {
        const float4 v = *reinterpret_cast<const float4*>(
            g_task_bin[b] + t * D_DIM + lane * 4);
        s.x += v.x; s.y += v.y; s.z += v.z; s.w += v.w;
    }
    float inv = 1.0f / tc;
    float4 m = make_float4(s.x * inv, s.y * inv, s.z * inv, s.w * inv);
    *reinterpret_cast<uint2*>(g_fph + (size_t)seg * D_DIM + lane * 4) = hpack4(m);
}

// ---------------- K4: uni_phenos gather -------------------------------------------
__global__ void k_uni_phenos(const float* __restrict__ phenos, float* __restrict__ out_uni) {
    int idx = blockIdx.x * blockDim.x + threadIdx.x;
    if (idx >= P_DIM * NP_DIM) return;
    int p = idx / NP_DIM;
    int j = idx - p * NP_DIM;
    int f = g_first[p];
    if (f > N_TOT - 1) f = N_TOT - 1;
    out_uni[idx] = phenos[(size_t)f * NP_DIM + j];
}

// =================================================================================
// fp16 mma.sync GEMM (R14 measured-best config): BK=128, 2-stage cp.async,
// block tile 128x256, 512 threads (16 warps as 2x8), warp tile 64x32, fp16 out.
// =================================================================================
#define A_STRIDE 136                                  // 128 data + 8 pad
#define B_STRIDE 264                                  // 256 data + 8 pad
#define SM_A 0
#define SM_B (128 * A_STRIDE)                         // 17408
#define STAGE_ELTS (SM_B + 128 * B_STRIDE)            // 51200 elts
#define STAGE_BYTES (STAGE_ELTS * 2)                  // 102400
#define SMEM_BYTES (2 * STAGE_BYTES)                  // 204800 bytes

__device__ __forceinline__ void cp16(uint32_t dst, const void* src, bool pred) {
    int sz = pred ? 16 : 0;
    asm volatile("cp.async.cg.shared.global [%0], [%1], 16, %2;\n"
                 :: "r"(dst), "l"(src), "r"(sz));
}
__device__ __forceinline__ void cp_commit() {
    asm volatile("cp.async.commit_group;\n");
}
template <int NG>
__device__ __forceinline__ void cp_wait() {
    asm volatile("cp.async.wait_group %0;\n" :: "n"(NG));
}
__device__ __forceinline__ void ldsm_x4(uint32_t* r, uint32_t addr) {
    asm volatile("ldmatrix.sync.aligned.m8n8.x4.shared.b16 {%0,%1,%2,%3}, [%4];"
                 : "=r"(r[0]), "=r"(r[1]), "=r"(r[2]), "=r"(r[3]) : "r"(addr));
}
__device__ __forceinline__ void ldsm_x4_t(uint32_t* r, uint32_t addr) {
    asm volatile("ldmatrix.sync.aligned.m8n8.x4.trans.shared.b16 {%0,%1,%2,%3}, [%4];"
                 : "=r"(r[0]), "=r"(r[1]), "=r"(r[2]), "=r"(r[3]) : "r"(addr));
}
__device__ __forceinline__ void mma_f16(float* d, const uint32_t* a, uint32_t b0, uint32_t b1) {
    asm volatile("mma.sync.aligned.m16n8k16.row.col.f32.f16.f16.f32 "
                 "{%0,%1,%2,%3},{%4,%5,%6,%7},{%8,%9},{%0,%1,%2,%3};"
                 : "+f"(d[0]), "+f"(d[1]), "+f"(d[2]), "+f"(d[3])
                 : "r"(a[0]), "r"(a[1]), "r"(a[2]), "r"(a[3]), "r"(b0), "r"(b1));
}

// stage loader (BK=128): 512 threads, 12 cp.async each
__device__ __forceinline__ void load_stage(
    uint32_t stage, const __half* A, const __half* B,
    int M, int N, int K, int blockM, int blockN, int k0, int tid) {
#pragma unroll
    for (int i = 0; i < 4; i++) {
        int c = tid + i * 512;
        int arow = c >> 4;
        int achk = (c & 15) << 3;
        int grow = blockM + arow;
        bool ap = grow < M;
        size_t goff = (size_t)grow * K + k0 + achk;
        uint32_t soff = stage + (uint32_t)((arow * A_STRIDE + achk) * 2);
        cp16(soff + SM_A * 2, A + goff, ap);
    }
#pragma unroll
    for (int i = 0; i < 8; i++) {
        int idx = tid + i * 512;
        int brow = idx >> 5;
        int bchk = (idx & 31) << 3;
        size_t gb = (size_t)(k0 + brow) * N + blockN + bchk;
        uint32_t sb = stage + (uint32_t)((brow * B_STRIDE + bchk) * 2);
        cp16(sb + SM_B * 2, B + gb, true);
    }
}

__global__ __launch_bounds__(512, 1) void k_mma_gemm(
    int M, int N, int K,
    const __half* __restrict__ A, const __half* __restrict__ B,
    const float* __restrict__ bias,
    __half* __restrict__ Ch) {
    extern __shared__ char sm_raw[];
    const uint32_t smbase = (uint32_t)__cvta_generic_to_shared(sm_raw);

    const int tid = threadIdx.x;
    const int lane = tid & 31;
    const int wid = tid >> 5;
    const int warpM = wid >> 3;     // 0..1
    const int warpN = wid & 7;      // 0..7
    const int blockM = blockIdx.y * 128;
    const int blockN = blockIdx.x * 256;

    float acc[4][4][4];
#pragma unroll
    for (int i = 0; i < 4; i++)
#pragma unroll
        for (int j = 0; j < 4; j++)
#pragma unroll
            for (int c = 0; c < 4; c++) acc[i][j][c] = 0.0f;

    const int lq = lane >> 4;
    const int lr = lane & 15;
    const int nStages = K >> 7;

    load_stage(smbase, A, B, M, N, K, blockM, blockN, 0, tid);
    cp_commit();

    for (int t = 0; t < nStages; t++) {
        if (t + 1 < nStages) {
            load_stage(smbase + (uint32_t)(((t + 1) & 1) * STAGE_BYTES),
                       A, B, M, N, K, blockM, blockN, (t + 1) << 7, tid);
            cp_commit();
            cp_wait<1>();
        } else {
            cp_wait<0>();
        }
        __syncthreads();

        const uint32_t stage = smbase + (uint32_t)((t & 1) * STAGE_BYTES);
#pragma unroll
        for (int kk = 0; kk < 128; kk += 16) {
            uint32_t a_r[4][4], b_r[2][4];
#pragma unroll
            for (int im = 0; im < 4; im++) {
                int row = warpM * 64 + im * 16 + lr;
                int col = kk + 8 * lq;
                uint32_t addr = stage + (uint32_t)((row * A_STRIDE + col) * 2);
                ldsm_x4(a_r[im], addr + SM_A * 2);
            }
#pragma unroll
            for (int ip = 0; ip < 2; ip++) {
                int row = kk + lr;
                int col = warpN * 32 + ip * 16 + 8 * lq;
                uint32_t addr = stage + (uint32_t)((row * B_STRIDE + col) * 2);
                ldsm_x4_t(b_r[ip], addr + SM_B * 2);
            }
#pragma unroll
            for (int im = 0; im < 4; im++) {
#pragma unroll
                for (int in = 0; in < 4; in++) {
                    int ip = in >> 1, h = (in & 1) << 1;
                    mma_f16(acc[im][in], a_r[im], b_r[ip][h], b_r[ip][h + 1]);
                }
            }
        }
        __syncthreads();
    }

    // epilogue: bias + relu -> fp16
    const int g = lane >> 2, tg = lane & 3;
#pragma unroll
    for (int im = 0; im < 4; im++) {
#pragma unroll
        for (int in = 0; in < 4; in++) {
            int col = blockN + warpN * 32 + in * 8 + tg * 2;
            float b0 = bias[col], b1 = bias[col + 1];
            int row0 = blockM + warpM * 64 + im * 16 + g;
            float v0 = fmaxf(acc[im][in][0] + b0, 0.f);
            float v1 = fmaxf(acc[im][in][1] + b1, 0.f);
            float v2 = fmaxf(acc[im][in][2] + b0, 0.f);
            float v3 = fmaxf(acc[im][in][3] + b1, 0.f);
            if (row0 < M) {
                __half2 hh = __floats2half2_rn(v0, v1);
                *reinterpret_cast<__half2*>(Ch + (size_t)row0 * N + col) = hh;
            }
            if (row0 + 8 < M) {
                __half2 hh = __floats2half2_rn(v2, v3);
                *reinterpret_cast<__half2*>(Ch + (size_t)(row0 + 8) * N + col) = hh;
            }
        }
    }
}

// ---------------- K6: head (fp16 h2) ----------------------------------------------
__global__ __launch_bounds__(256) void k_head(
    const __half* __restrict__ h, const float* __restrict__ W3,
    const float* __restrict__ b3,
    float* __restrict__ out_sig, float* __restrict__ out_latent) {
    int p = blockIdx.x;
    int tid = threadIdx.x;
    int lane = tid & 31;
    int wid = tid >> 5;

    float acc[NP_DIM];
#pragma unroll
    for (int j = 0; j < NP_DIM; j++) acc[j] = 0.0f;

    const __half* hrow = h + (size_t)p * H_DIM;
    for (int k = tid; k < H_DIM; k += 256) {
        float hv = __half2float(hrow[k]);
        const float* w = W3 + (size_t)k * NP_DIM;
#pragma unroll
        for (int j = 0; j < NP_DIM; j++) acc[j] = fmaf(hv, w[j], acc[j]);
    }
#pragma unroll
    for (int j = 0; j < NP_DIM; j++) {
#pragma unroll
        for (int s = 16; s > 0; s >>= 1)
            acc[j] += __shfl_down_sync(0xFFFFFFFF, acc[j], s);
    }
    __shared__ float smem[8][NP_DIM];
    if (lane == 0) {
#pragma unroll
        for (int j = 0; j < NP_DIM; j++) smem[wid][j] = acc[j];
    }
    __syncthreads();
    if (tid < NP_DIM) {
        float s = 0.0f;
#pragma unroll
        for (int w = 0; w < 8; w++) s += smem[w][tid];
        float latent = s + b3[tid];
        out_latent[p * NP_DIM + tid] = latent;
        out_sig[p * NP_DIM + tid] = 1.0f / (1.0f + expf(-latent));
    }
}

// ---------------- launch ----------------------------------------------------
extern "C" void kernel_launch(void* const* d_in, const int* in_sizes, int n_in,
                              void* d_out, int out_size) {
    const float* motion_z    = (const float*)d_in[0];
    const int*   tasks       = (const int*)d_in[1];
    const int*   tasks_mask  = (const int*)d_in[2];
    const int*   patient_ids = (const int*)d_in[3];
    const float* phenos      = (const float*)d_in[4];
    const int*   phenos_mask = (const int*)d_in[5];
    const float* W1          = (const float*)d_in[6];
    const float* b1          = (const float*)d_in[7];
    const float* W2          = (const float*)d_in[8];
    const float* b2          = (const float*)d_in[9];
    const float* W3          = (const float*)d_in[10];
    const float* b3          = (const float*)d_in[11];

    float* out_sig    = (float*)d_out;
    float* out_uni    = out_sig + P_DIM * NP_DIM;
    float* out_latent = out_uni + P_DIM * NP_DIM;

    __half *fph, *w1h, *w2h, *h1h, *h2h;
    cudaGetSymbolAddress((void**)&fph, g_fph);
    cudaGetSymbolAddress((void**)&w1h, g_W1h);
    cudaGetSymbolAddress((void**)&w2h, g_W2h);
    cudaGetSymbolAddress((void**)&h1h, g_h1h);
    cudaGetSymbolAddress((void**)&h2h, g_h2h);

    cudaFuncSetAttribute(k_mma_gemm, cudaFuncAttributeMaxDynamicSharedMemorySize, SMEM_BYTES);

    k_init<<<64, 256>>>();                                                      // 1
    k_place<<<(N_TOT + 255) / 256, 256>>>(tasks, tasks_mask, patient_ids,
                                          phenos_mask);                         // 2
    k_combo<<<COMBO_GRID, 256>>>(motion_z, W1, w1h, W2, w2h);                   // 3
    k_fallback<<<PT / 8, 256>>>();                                              // 4
    k_uni_phenos<<<(P_DIM * NP_DIM + 255) / 256, 256>>>(phenos, out_uni);       // 5

    // GEMM1: [2000,1024] @ [1024,2048] -> h1 (relu, fp16 out)                  // 6
    {
        dim3 grid(H_DIM / 256, (P_DIM + 127) / 128);   // 8 x 16
        k_mma_gemm<<<grid, 512, SMEM_BYTES>>>(P_DIM, H_DIM, TD, fph, w1h, b1, h1h);
    }
    // GEMM2: [2000,2048] @ [2048,2048] -> h2 (relu, fp16 out)                  // 7
    {
        dim3 grid(H_DIM / 256, (P_DIM + 127) / 128);
        k_mma_gemm<<<grid, 512, SMEM_BYTES>>>(P_DIM, H_DIM, H_DIM, h1h, w2h, b2, h2h);
    }
    k_head<<<P_DIM, 256>>>(h2h, W3, b3, out_sig, out_latent);                   // 8
}